// round 5
// baseline (speedup 1.0000x reference)
#include <cuda_runtime.h>
#include <math.h>
#include <float.h>

#define PI_F 3.14159265358979323846f

// ----------------------------- static scratch -----------------------------
__device__ float2 g_spec[16 * 512 * 512];        // 32 MB
__device__ float  g_mag [16 * 512 * 512];        // 16 MB
__device__ float  g_grad[16 * 2 * 512 * 512];    // 32 MB
__device__ float  g_h1  [16 * 32 * 256 * 256];   // 128 MB
__device__ float  g_c1  [16 * 32768];
__device__ float  g_c2  [16 * 4096];
__device__ float  g_c3  [16 * 512];
__device__ float  g_dom [16 * 128];
__device__ float  g_sims[16 * 64];
__device__ float  g_pool[16 * 64 * 16];
__device__ double g_psum[16];
__device__ double g_psumsq[16];
__device__ int    g_hist[16 * 64];

// ----------------------------- init -----------------------------
__global__ void zero_k() {
    int tid = blockIdx.x * blockDim.x + threadIdx.x;
    int nt = gridDim.x * blockDim.x;
    for (int i = tid; i < 16 * 64 * 16; i += nt) g_pool[i] = 0.f;
    for (int i = tid; i < 16 * 64; i += nt) g_hist[i] = 0;
    for (int i = tid; i < 16; i += nt) { g_psum[i] = 0.0; g_psumsq[i] = 0.0; }
}

// ----------------------------- 512-pt FFT (256 threads) -----------------------------
__device__ __forceinline__ void fft512(float2* s, const float2* tw) {
    int tid = threadIdx.x;
    __syncthreads();
    for (int i = tid; i < 512; i += 256) {
        int j = __brev(i) >> 23;
        if (j > i) { float2 t = s[i]; s[i] = s[j]; s[j] = t; }
    }
    __syncthreads();
    #pragma unroll
    for (int st = 0; st < 9; ++st) {
        int half = 1 << st;
        int pos = tid & (half - 1);
        int i0 = ((tid >> st) << (st + 1)) + pos;
        int i1 = i0 + half;
        float2 w = tw[pos << (8 - st)];
        float2 a = s[i0], b = s[i1];
        float2 t = make_float2(w.x * b.x - w.y * b.y, w.x * b.y + w.y * b.x);
        s[i0] = make_float2(a.x + t.x, a.y + t.y);
        s[i1] = make_float2(a.x - t.x, a.y - t.y);
        __syncthreads();
    }
}

__global__ void __launch_bounds__(256) fft_rows_k(const float* __restrict__ img) {
    __shared__ float2 s[512];
    __shared__ float2 tw[256];
    int b = blockIdx.x >> 9, row = blockIdx.x & 511;
    int tid = threadIdx.x;
    const float* p = img + (((size_t)b << 9) + row) * 512;
    for (int i = tid; i < 512; i += 256) s[i] = make_float2(p[i], 0.f);
    { float sc, cc; sincosf(-2.f * PI_F * (float)tid / 512.f, &sc, &cc); tw[tid] = make_float2(cc, sc); }
    fft512(s, tw);
    __syncthreads();
    for (int c = tid; c < 512; c += 256)
        g_spec[(((size_t)(b * 512 + c)) << 9) + row] = s[c];
}

__global__ void __launch_bounds__(256) fft_cols_k() {
    __shared__ float2 s[512];
    __shared__ float2 tw[256];
    __shared__ float rsum[256], rsq[256];
    __shared__ int lhist[64];
    int b = blockIdx.x >> 9;
    int tid = threadIdx.x;
    size_t base = ((size_t)blockIdx.x) << 9;
    for (int i = tid; i < 512; i += 256) s[i] = g_spec[base + i];
    { float sc, cc; sincosf(-2.f * PI_F * (float)tid / 512.f, &sc, &cc); tw[tid] = make_float2(cc, sc); }
    if (tid < 64) lhist[tid] = 0;
    fft512(s, tw);
    __syncthreads();
    float lsum = 0.f, lsq = 0.f;
    for (int i = tid; i < 512; i += 256) {
        float2 v = s[i];
        g_mag[base + i] = sqrtf(v.x * v.x + v.y * v.y);
        float ph = atan2f(v.y, v.x);
        lsum += ph; lsq += ph * ph;
        int bin = (int)floorf((ph + PI_F) * (64.f / (2.f * PI_F)));
        bin = min(max(bin, 0), 63);
        atomicAdd(&lhist[bin], 1);
    }
    rsum[tid] = lsum; rsq[tid] = lsq;
    __syncthreads();
    for (int st = 128; st > 0; st >>= 1) {
        if (tid < st) { rsum[tid] += rsum[tid + st]; rsq[tid] += rsq[tid + st]; }
        __syncthreads();
    }
    if (tid == 0) {
        atomicAdd(&g_psum[b], (double)rsum[0]);
        atomicAdd(&g_psumsq[b], (double)rsq[0]);
    }
    if (tid < 64) atomicAdd(&g_hist[b * 64 + tid], lhist[tid]);
}

// ----------------------------- hierarchical top-128 (bitonic) -----------------------------
__global__ void __launch_bounds__(512) topk_k(int stage) {
    __shared__ float s[1024];
    const float* in; float* outp; int L, chunks;
    if (stage == 0)      { in = g_mag; outp = g_c1;  L = 262144; chunks = 256; }
    else if (stage == 1) { in = g_c1;  outp = g_c2;  L = 32768;  chunks = 32;  }
    else if (stage == 2) { in = g_c2;  outp = g_c3;  L = 4096;   chunks = 4;   }
    else                 { in = g_c3;  outp = g_dom; L = 512;    chunks = 1;   }
    int b = blockIdx.x / chunks, ch = blockIdx.x % chunks;
    int tid = threadIdx.x;
    const float* p = in + (size_t)b * L + (size_t)ch * 1024;
    int rem = L - ch * 1024;
    for (int i = tid; i < 1024; i += 512) s[i] = (i < rem) ? p[i] : -FLT_MAX;
    __syncthreads();
    for (int k = 2; k <= 1024; k <<= 1) {
        for (int j = k >> 1; j > 0; j >>= 1) {
            for (int i = tid; i < 1024; i += 512) {
                int ixj = i ^ j;
                if (ixj > i) {
                    float a = s[i], bb = s[ixj];
                    if ((a > bb) == ((i & k) == 0)) { s[i] = bb; s[ixj] = a; }
                }
            }
            __syncthreads();
        }
    }
    if (tid < 128)
        outp[(size_t)(b * chunks + ch) * 128 + tid] = s[1023 - tid];
}

// ----------------------------- sims -----------------------------
__global__ void __launch_bounds__(64) sims_k(const float* __restrict__ rec) {
    __shared__ float dm[128];
    __shared__ float red[64];
    int b = blockIdx.x, tid = threadIdx.x;
    dm[tid] = g_dom[b * 128 + tid];
    dm[tid + 64] = g_dom[b * 128 + 64 + tid];
    __syncthreads();
    red[tid] = dm[tid] * dm[tid] + dm[tid + 64] * dm[tid + 64];
    __syncthreads();
    for (int st = 32; st > 0; st >>= 1) {
        if (tid < st) red[tid] += red[tid + st];
        __syncthreads();
    }
    float nd = fmaxf(sqrtf(red[0]), 1e-12f);
    const float* r = rec + tid * 128;
    float dot = 0.f, nr = 0.f;
    #pragma unroll 4
    for (int k = 0; k < 128; ++k) {
        float rv = r[k];
        dot = fmaf(dm[k], rv, dot);
        nr = fmaf(rv, rv, nr);
    }
    g_sims[b * 64 + tid] = dot / (nd * fmaxf(sqrtf(nr), 1e-12f));
}

// ----------------------------- gradients -----------------------------
__global__ void __launch_bounds__(256) grad_k(const float* __restrict__ img) {
    int n = 16 * 512 * 512;
    for (int idx = blockIdx.x * blockDim.x + threadIdx.x; idx < n; idx += gridDim.x * blockDim.x) {
        int x = idx & 511, y = (idx >> 9) & 511, b = idx >> 18;
        const float* p = img + ((size_t)b << 18);
        float c = p[(y << 9) | x];
        float gy, gx;
        if (y == 0)        gy = p[(1 << 9) | x] - c;
        else if (y == 511) gy = c - p[(510 << 9) | x];
        else               gy = 0.5f * (p[((y + 1) << 9) | x] - p[((y - 1) << 9) | x]);
        if (x == 0)        gx = p[(y << 9) | 1] - c;
        else if (x == 511) gx = c - p[(y << 9) | 510];
        else               gx = 0.5f * (p[(y << 9) | (x + 1)] - p[(y << 9) | (x - 1)]);
        g_grad[(((size_t)b * 2 + 0) << 18) + idx % 262144] = sqrtf(gx * gx + gy * gy);
        g_grad[(((size_t)b * 2 + 1) << 18) + idx % 262144] = atan2f(gy, gx);
    }
}

// ----------------------------- conv1 (2->32 3x3 relu) + maxpool2 -----------------------------
__global__ void __launch_bounds__(256) conv1pool_k(const float* __restrict__ w, const float* __restrict__ bias) {
    __shared__ __align__(16) float gin[2][66][68];
    __shared__ float wsh[32][18];
    __shared__ float bsh[32];
    int b = blockIdx.z;
    int CY = blockIdx.y * 64, CX = blockIdx.x * 64;
    int PY = blockIdx.y * 32, PX = blockIdx.x * 32;
    int tid = threadIdx.x;
    for (int i = tid; i < 2 * 66 * 66; i += 256) {
        int c = i / (66 * 66), rem = i % (66 * 66);
        int r = rem / 66, x = rem % 66;
        int gy = CY - 1 + r, gx = CX - 1 + x;
        float v = 0.f;
        if ((unsigned)gy < 512u && (unsigned)gx < 512u)
            v = g_grad[(((size_t)(b * 2 + c)) << 18) + (gy << 9) + gx];
        gin[c][r][x] = v;
    }
    for (int i = tid; i < 576; i += 256) wsh[i / 18][i % 18] = w[i];
    if (tid < 32) bsh[tid] = bias[tid];
    __syncthreads();

    int ppx0 = (tid & 7) * 4, ppy = tid >> 3;
    int cy0 = ppy * 2, cx0 = ppx0 * 2;
    float rin[2][4][10];
    #pragma unroll
    for (int c = 0; c < 2; ++c)
        #pragma unroll
        for (int r = 0; r < 4; ++r) {
            const float* bp = &gin[c][cy0 + r][cx0];
            float4 a = *(const float4*)bp;
            float4 q = *(const float4*)(bp + 4);
            float2 e = *(const float2*)(bp + 8);
            rin[c][r][0] = a.x; rin[c][r][1] = a.y; rin[c][r][2] = a.z; rin[c][r][3] = a.w;
            rin[c][r][4] = q.x; rin[c][r][5] = q.y; rin[c][r][6] = q.z; rin[c][r][7] = q.w;
            rin[c][r][8] = e.x; rin[c][r][9] = e.y;
        }
    for (int oc = 0; oc < 32; ++oc) {
        float wl[2][9];
        #pragma unroll
        for (int c = 0; c < 2; ++c)
            #pragma unroll
            for (int t = 0; t < 9; ++t) wl[c][t] = wsh[oc][c * 9 + t];
        float bb = bsh[oc];
        #pragma unroll
        for (int pp = 0; pp < 4; ++pp) {
            float vmax = -FLT_MAX;
            #pragma unroll
            for (int r = 0; r < 2; ++r)
                #pragma unroll
                for (int cc = 0; cc < 2; ++cc) {
                    float v = bb;
                    #pragma unroll
                    for (int c = 0; c < 2; ++c)
                        #pragma unroll
                        for (int ky = 0; ky < 3; ++ky)
                            #pragma unroll
                            for (int kx = 0; kx < 3; ++kx)
                                v = fmaf(rin[c][r + ky][2 * pp + cc + kx], wl[c][ky * 3 + kx], v);
                    vmax = fmaxf(vmax, v);
                }
            g_h1[(((size_t)(b * 32 + oc)) * 256 + (PY + ppy)) * 256 + (PX + ppx0 + pp)] = fmaxf(vmax, 0.f);
        }
    }
}

// ----------------------------- conv2 (32->64 3x3, bias+relu) + 64x64 avg-pool sums -----------------------------
__global__ void __launch_bounds__(128) conv2pool_k(const float* __restrict__ w, const float* __restrict__ bias) {
    __shared__ __align__(16) float sin_[8][34][36];
    __shared__ float wsh[8][8][9];
    __shared__ float pools[8];
    int b = blockIdx.z;
    int ocg = blockIdx.y;
    int tile = blockIdx.x;
    int TY = (tile >> 3) * 32, TX = (tile & 7) * 32;
    int tid = threadIdx.x;
    int px0 = (tid & 7) * 4, py0 = (tid >> 3) * 2;
    float acc[8][8];
    #pragma unroll
    for (int o = 0; o < 8; ++o)
        #pragma unroll
        for (int p = 0; p < 8; ++p) acc[o][p] = 0.f;

    for (int chk = 0; chk < 4; ++chk) {
        __syncthreads();
        for (int i = tid; i < 8 * 34 * 34; i += 128) {
            int l = i / (34 * 34), rem = i % (34 * 34);
            int r = rem / 34, c = rem % 34;
            int gy = TY + r - 1, gx = TX + c - 1;
            float v = 0.f;
            if ((unsigned)gy < 256u && (unsigned)gx < 256u)
                v = g_h1[(((size_t)(b * 32 + chk * 8 + l)) * 256 + gy) * 256 + gx];
            sin_[l][r][c] = v;
        }
        for (int i = tid; i < 8 * 8 * 9; i += 128) {
            int ol = i / 72, rem = i % 72;
            wsh[ol][rem / 9][rem % 9] = w[(size_t)((ocg * 8 + ol) * 32 + chk * 8 + rem / 9) * 9 + rem % 9];
        }
        __syncthreads();
        for (int il = 0; il < 8; ++il) {
            float rin[4][6];
            #pragma unroll
            for (int r = 0; r < 4; ++r) {
                const float* bp = &sin_[il][py0 + r][px0];
                float4 v4 = *(const float4*)bp;
                float2 v2 = *(const float2*)(bp + 4);
                rin[r][0] = v4.x; rin[r][1] = v4.y; rin[r][2] = v4.z; rin[r][3] = v4.w;
                rin[r][4] = v2.x; rin[r][5] = v2.y;
            }
            #pragma unroll
            for (int ol = 0; ol < 8; ++ol) {
                #pragma unroll
                for (int ky = 0; ky < 3; ++ky) {
                    float w0 = wsh[ol][il][ky * 3 + 0];
                    float w1 = wsh[ol][il][ky * 3 + 1];
                    float w2 = wsh[ol][il][ky * 3 + 2];
                    #pragma unroll
                    for (int r = 0; r < 2; ++r)
                        #pragma unroll
                        for (int c = 0; c < 4; ++c) {
                            float v = acc[ol][r * 4 + c];
                            v = fmaf(rin[r + ky][c + 0], w0, v);
                            v = fmaf(rin[r + ky][c + 1], w1, v);
                            v = fmaf(rin[r + ky][c + 2], w2, v);
                            acc[ol][r * 4 + c] = v;
                        }
                }
            }
        }
    }
    __syncthreads();
    if (tid < 8) pools[tid] = 0.f;
    __syncthreads();
    #pragma unroll
    for (int ol = 0; ol < 8; ++ol) {
        float bb = bias[ocg * 8 + ol];
        float ssum = 0.f;
        #pragma unroll
        for (int p = 0; p < 8; ++p) ssum += fmaxf(acc[ol][p] + bb, 0.f);
        atomicAdd(&pools[ol], ssum);
    }
    __syncthreads();
    if (tid < 8) {
        int cell = (TY >> 6) * 4 + (TX >> 6);
        atomicAdd(&g_pool[b * 1024 + (ocg * 8 + tid) * 16 + cell], pools[tid]);
    }
}

// ----------------------------- fuse: combined -> fc1 -> fc2 -> layernorm -----------------------------
__global__ void __launch_bounds__(256) fuse_k(
    const float* __restrict__ fc1_w, const float* __restrict__ fc1_b,
    const float* __restrict__ fc2_w, const float* __restrict__ fc2_b,
    const float* __restrict__ ln_g, const float* __restrict__ ln_b,
    float* __restrict__ out)
{
    __shared__ float comb[1091];
    __shared__ float z[512];
    __shared__ float z2[128];
    __shared__ float stats[2];
    int b = blockIdx.x, tid = threadIdx.x;
    for (int i = tid; i < 64; i += 256) {
        float v = g_sims[b * 64 + i];
        comb[i] = v;
        out[b * 64 + i] = v;
    }
    for (int i = tid; i < 1024; i += 256) {
        float v = g_pool[b * 1024 + i] * (1.f / 4096.f);
        comb[64 + i] = v;
        out[1024 + b * 1024 + i] = v;
    }
    if (tid == 0) {
        const double N = 262144.0;
        double mean = g_psum[b] / N;
        double var = (g_psumsq[b] - N * mean * mean) / (N - 1.0);
        float ent = 0.f;
        for (int k = 0; k < 64; ++k) {
            float h = (float)g_hist[b * 64 + k] * (1.f / 262144.f);
            ent -= h * logf(h + 1e-10f);
        }
        comb[1088] = (float)mean;
        comb[1089] = (float)sqrt(var);
        comb[1090] = ent;
        out[17408 + b * 3 + 0] = comb[1088];
        out[17408 + b * 3 + 1] = comb[1089];
        out[17408 + b * 3 + 2] = comb[1090];
    }
    __syncthreads();
    for (int j = tid; j < 512; j += 256) {
        const float* wr = fc1_w + (size_t)j * 1091;
        float a0 = fc1_b[j];
        #pragma unroll 4
        for (int k = 0; k < 1091; ++k) a0 = fmaf(comb[k], wr[k], a0);
        z[j] = fmaxf(a0, 0.f);
    }
    __syncthreads();
    if (tid < 128) {
        const float* wr = fc2_w + (size_t)tid * 512;
        float a0 = fc2_b[tid];
        #pragma unroll 4
        for (int k = 0; k < 512; ++k) a0 = fmaf(z[k], wr[k], a0);
        z2[tid] = a0;
    }
    __syncthreads();
    if (tid == 0) {
        float mu = 0.f;
        for (int k = 0; k < 128; ++k) mu += z2[k];
        mu *= (1.f / 128.f);
        float var = 0.f;
        for (int k = 0; k < 128; ++k) { float d = z2[k] - mu; var += d * d; }
        var *= (1.f / 128.f);
        stats[0] = mu;
        stats[1] = rsqrtf(var + 1e-5f);
    }
    __syncthreads();
    if (tid < 128)
        out[17456 + b * 128 + tid] = (z2[tid] - stats[0]) * stats[1] * ln_g[tid] + ln_b[tid];
}

// ----------------------------- launch -----------------------------
extern "C" void kernel_launch(void* const* d_in, const int* in_sizes, int n_in,
                              void* d_out, int out_size) {
    const float* image = (const float*)d_in[0];
    const float* rec   = (const float*)d_in[1];
    const float* c1w   = (const float*)d_in[2];
    const float* c1b   = (const float*)d_in[3];
    const float* c2w   = (const float*)d_in[4];
    const float* c2b   = (const float*)d_in[5];
    const float* fc1w  = (const float*)d_in[6];
    const float* fc1b  = (const float*)d_in[7];
    const float* fc2w  = (const float*)d_in[8];
    const float* fc2b  = (const float*)d_in[9];
    const float* lng   = (const float*)d_in[10];
    const float* lnb   = (const float*)d_in[11];
    float* out = (float*)d_out;

    zero_k<<<64, 256>>>();
    fft_rows_k<<<16 * 512, 256>>>(image);
    fft_cols_k<<<16 * 512, 256>>>();
    topk_k<<<16 * 256, 512>>>(0);
    topk_k<<<16 * 32, 512>>>(1);
    topk_k<<<16 * 4, 512>>>(2);
    topk_k<<<16, 512>>>(3);
    sims_k<<<16, 64>>>(rec);
    grad_k<<<1024, 256>>>(image);
    conv1pool_k<<<dim3(8, 8, 16), 256>>>(c1w, c1b);
    conv2pool_k<<<dim3(64, 8, 16), 128>>>(c2w, c2b);
    fuse_k<<<16, 256>>>(fc1w, fc1b, fc2w, fc2b, lng, lnb, out);
}